// round 4
// baseline (speedup 1.0000x reference)
#include <cuda_runtime.h>
#include <cuda_fp16.h>

#define N_NODES   50000
#define IN_FEATS  256
#define OUT_FEATS 128
#define MAX_E     800000

// ---- scratch (device globals; no allocs allowed) ----
__device__ __half g_hw[(size_t)N_NODES * OUT_FEATS];  // projected features (fp16)
__device__ int    g_counts[N_NODES];                  // in-degree histogram
__device__ int    g_row_ptr[N_NODES + 1];             // CSR row offsets (by dst)
__device__ int    g_cursor[N_NODES];                  // fill cursors
__device__ int    g_perm_src[MAX_E];                  // src per CSR slot
__device__ float  g_perm_c[MAX_E];                    // coeff per CSR slot

// ===========================================================================
// Kernel: SGEMM hw[M,128] = h[M,256] @ W[256,128]  (fp32 math, fp16 store)
// 128x128 block tile, BK=16, 256 threads, 8x8 micro-tile, A transposed in smem.
// ===========================================================================
#define GBM 128
#define GBN 128
#define GBK 16

__global__ __launch_bounds__(256) void gemm_kernel(
    const float* __restrict__ h, const float* __restrict__ W, int M)
{
    __shared__ float As[GBK][GBM + 4];   // K-major: As[k][m]
    __shared__ float Bs[GBK][GBN];

    const int tid  = threadIdx.x;
    const int tcol = tid & 15;    // output cols tcol*8..+7
    const int trow = tid >> 4;    // output rows trow*8..+7
    const int block_m = blockIdx.x * GBM;

    float acc[8][8];
#pragma unroll
    for (int i = 0; i < 8; i++)
#pragma unroll
        for (int j = 0; j < 8; j++) acc[i][j] = 0.f;

    for (int k0 = 0; k0 < IN_FEATS; k0 += GBK) {
#pragma unroll
        for (int l = 0; l < 2; l++) {
            int idx = tid + l * 256;
            int r   = idx >> 2;
            int c4  = idx & 3;
            int gr  = block_m + r;
            float4 v = make_float4(0.f, 0.f, 0.f, 0.f);
            if (gr < M)
                v = *reinterpret_cast<const float4*>(h + (size_t)gr * IN_FEATS + k0 + c4 * 4);
            As[c4 * 4 + 0][r] = v.x;
            As[c4 * 4 + 1][r] = v.y;
            As[c4 * 4 + 2][r] = v.z;
            As[c4 * 4 + 3][r] = v.w;
        }
#pragma unroll
        for (int l = 0; l < 2; l++) {
            int idx = tid + l * 256;
            int r   = idx >> 5;
            int c4  = idx & 31;
            *reinterpret_cast<float4*>(&Bs[r][c4 * 4]) =
                *reinterpret_cast<const float4*>(W + (size_t)(k0 + r) * GBN + c4 * 4);
        }
        __syncthreads();

#pragma unroll
        for (int k = 0; k < GBK; k++) {
            float4 a0 = *reinterpret_cast<const float4*>(&As[k][trow * 8]);
            float4 a1 = *reinterpret_cast<const float4*>(&As[k][trow * 8 + 4]);
            float4 b0 = *reinterpret_cast<const float4*>(&Bs[k][tcol * 8]);
            float4 b1 = *reinterpret_cast<const float4*>(&Bs[k][tcol * 8 + 4]);
            float a[8] = {a0.x, a0.y, a0.z, a0.w, a1.x, a1.y, a1.z, a1.w};
            float b[8] = {b0.x, b0.y, b0.z, b0.w, b1.x, b1.y, b1.z, b1.w};
#pragma unroll
            for (int i = 0; i < 8; i++)
#pragma unroll
                for (int j = 0; j < 8; j++)
                    acc[i][j] = fmaf(a[i], b[j], acc[i][j]);
        }
        __syncthreads();
    }

#pragma unroll
    for (int i = 0; i < 8; i++) {
        int gr = block_m + trow * 8 + i;
        if (gr < M) {
            __half2 p[4];
#pragma unroll
            for (int j = 0; j < 4; j++)
                p[j] = __floats2half2_rn(acc[i][2 * j], acc[i][2 * j + 1]);
            *reinterpret_cast<uint2*>(&g_hw[(size_t)gr * GBN + tcol * 8]) =
                *reinterpret_cast<uint2*>(&p[0]);
            *reinterpret_cast<uint2*>(&g_hw[(size_t)gr * GBN + tcol * 8 + 4]) =
                *reinterpret_cast<uint2*>(&p[2]);
        }
    }
}

// ===========================================================================
// CSR build
// ===========================================================================
__global__ void zero_counts_kernel(int N)
{
    int i = blockIdx.x * blockDim.x + threadIdx.x;
    if (i < N) g_counts[i] = 0;
}

__global__ void hist_kernel(const int* __restrict__ dst, int E)
{
    int e = blockIdx.x * blockDim.x + threadIdx.x;
    if (e < E) atomicAdd(&g_counts[dst[e]], 1);
}

// Single-block fused exclusive scan over g_counts -> g_row_ptr / g_cursor.
// 1024 threads, 4 items/thread => 4096 elements per iteration, serial carry.
__global__ __launch_bounds__(1024) void scan_fused_kernel(int N, int E)
{
    __shared__ int warp_off[32];   // exclusive offset per warp within chunk
    __shared__ int chunk_total;

    const int tid  = threadIdx.x;
    const int lane = tid & 31;
    const int wid  = tid >> 5;

    int carry = 0;
    for (int base = 0; base < N; base += 4096) {
        int idx = base + tid * 4;
        int v[4];
#pragma unroll
        for (int k = 0; k < 4; k++)
            v[k] = (idx + k < N) ? g_counts[idx + k] : 0;
        int tsum = v[0] + v[1] + v[2] + v[3];

        // inclusive warp scan of per-thread sums
        int s = tsum;
#pragma unroll
        for (int o = 1; o < 32; o <<= 1) {
            int t = __shfl_up_sync(0xffffffffu, s, o);
            if (lane >= o) s += t;
        }
        if (lane == 31) warp_off[wid] = s;   // warp total (inclusive)
        __syncthreads();

        if (wid == 0) {
            int ws = warp_off[lane];
            int si = ws;
#pragma unroll
            for (int o = 1; o < 32; o <<= 1) {
                int t = __shfl_up_sync(0xffffffffu, si, o);
                if (lane >= o) si += t;
            }
            warp_off[lane] = si - ws;        // exclusive warp offset
            if (lane == 31) chunk_total = si;
        }
        __syncthreads();

        int running = carry + warp_off[wid] + (s - tsum);
#pragma unroll
        for (int k = 0; k < 4; k++) {
            if (idx + k < N) {
                g_row_ptr[idx + k] = running;
                g_cursor[idx + k]  = running;
            }
            running += v[k];
        }
        carry += chunk_total;
        __syncthreads();   // protect warp_off/chunk_total for next iteration
    }
    if (tid == 0) g_row_ptr[N] = E;
}

// permutation: bucket edges by dst, precompute coefficient
__global__ void permute_kernel(
    const int* __restrict__ src, const int* __restrict__ dst,
    const float* __restrict__ norm, const float* __restrict__ ew, int E)
{
    int e = blockIdx.x * blockDim.x + threadIdx.x;
    if (e >= E) return;
    int s = src[e];
    int d = dst[e];
    int pos = atomicAdd(&g_cursor[d], 1);
    g_perm_src[pos] = s;
    g_perm_c[pos]   = norm[s] * ew[e];
}

// ===========================================================================
// Gather-aggregate per destination node + fused finalize.
// One warp per node; lane handles 4 features (8 bytes of fp16 per edge).
// ===========================================================================
__global__ __launch_bounds__(256) void gather_kernel(
    const float* __restrict__ norm, const float* __restrict__ bias,
    float* __restrict__ out, int N)
{
    int d = blockIdx.x * 8 + (threadIdx.x >> 5);
    if (d >= N) return;
    int lane = threadIdx.x & 31;

    int j   = g_row_ptr[d];
    int end = g_row_ptr[d + 1];

    float ax = 0.f, ay = 0.f, az = 0.f, aw = 0.f;

    for (; j + 2 <= end; j += 2) {
        int   s0 = g_perm_src[j],   s1 = g_perm_src[j + 1];
        float c0 = g_perm_c[j],     c1 = g_perm_c[j + 1];
        uint2 r0 = *reinterpret_cast<const uint2*>(&g_hw[(size_t)s0 * OUT_FEATS + lane * 4]);
        uint2 r1 = *reinterpret_cast<const uint2*>(&g_hw[(size_t)s1 * OUT_FEATS + lane * 4]);
        float2 f00 = __half22float2(*reinterpret_cast<__half2*>(&r0.x));
        float2 f01 = __half22float2(*reinterpret_cast<__half2*>(&r0.y));
        float2 f10 = __half22float2(*reinterpret_cast<__half2*>(&r1.x));
        float2 f11 = __half22float2(*reinterpret_cast<__half2*>(&r1.y));
        ax = fmaf(c0, f00.x, ax); ay = fmaf(c0, f00.y, ay);
        az = fmaf(c0, f01.x, az); aw = fmaf(c0, f01.y, aw);
        ax = fmaf(c1, f10.x, ax); ay = fmaf(c1, f10.y, ay);
        az = fmaf(c1, f11.x, az); aw = fmaf(c1, f11.y, aw);
    }
    if (j < end) {
        int   s0 = g_perm_src[j];
        float c0 = g_perm_c[j];
        uint2 r0 = *reinterpret_cast<const uint2*>(&g_hw[(size_t)s0 * OUT_FEATS + lane * 4]);
        float2 f00 = __half22float2(*reinterpret_cast<__half2*>(&r0.x));
        float2 f01 = __half22float2(*reinterpret_cast<__half2*>(&r0.y));
        ax = fmaf(c0, f00.x, ax); ay = fmaf(c0, f00.y, ay);
        az = fmaf(c0, f01.x, az); aw = fmaf(c0, f01.y, aw);
    }

    float  nd = norm[d];
    float4 b  = reinterpret_cast<const float4*>(bias)[lane];
    float4 r;
    r.x = fmaxf(fmaf(ax, nd, b.x), 0.f);
    r.y = fmaxf(fmaf(ay, nd, b.y), 0.f);
    r.z = fmaxf(fmaf(az, nd, b.z), 0.f);
    r.w = fmaxf(fmaf(aw, nd, b.w), 0.f);
    reinterpret_cast<float4*>(out)[(size_t)d * 32 + lane] = r;
}

// ===========================================================================
// Launch: h, weight, bias, norm, edge_weight, edge_src, edge_dst
// Order chosen so gather_kernel is launch index 5 (ncu -s 5 -c 1 profiles it).
// ===========================================================================
extern "C" void kernel_launch(void* const* d_in, const int* in_sizes, int n_in,
                              void* d_out, int out_size)
{
    const float* h    = (const float*)d_in[0];
    const float* W    = (const float*)d_in[1];
    const float* bias = (const float*)d_in[2];
    const float* norm = (const float*)d_in[3];
    const float* ew   = (const float*)d_in[4];
    const int*   src  = (const int*)d_in[5];
    const int*   dst  = (const int*)d_in[6];
    float* out = (float*)d_out;

    const int N  = in_sizes[3];
    const int E  = in_sizes[4];

    zero_counts_kernel<<<(N + 255) / 256, 256>>>(N);                 // 0
    hist_kernel<<<(E + 255) / 256, 256>>>(dst, E);                   // 1
    scan_fused_kernel<<<1, 1024>>>(N, E);                            // 2
    permute_kernel<<<(E + 255) / 256, 256>>>(src, dst, norm, ew, E); // 3
    gemm_kernel<<<(N + GBM - 1) / GBM, 256>>>(h, W, N);              // 4
    gather_kernel<<<(N + 7) / 8, 256>>>(norm, bias, out, N);         // 5
}

// round 6
// speedup vs baseline: 1.9560x; 1.9560x over previous
#include <cuda_runtime.h>
#include <cuda_fp16.h>

#define N_NODES   50000
#define IN_FEATS  256
#define OUT_FEATS 128
#define MAX_E     800000

// ---- scratch (device globals; no allocs allowed) ----
__device__ __half g_hw[(size_t)N_NODES * OUT_FEATS];  // projected features (fp16)
__device__ int    g_counts[N_NODES];
__device__ int    g_row_ptr[N_NODES + 1];
__device__ int    g_cursor[N_NODES];
__device__ int    g_bsum[256];
__device__ int    g_boff[256];
__device__ int    g_perm_src[MAX_E];
__device__ float  g_perm_c[MAX_E];

// ===========================================================================
// PTX helpers
// ===========================================================================
__device__ __forceinline__ unsigned smem_addr_u32(const void* ptr)
{
    return static_cast<unsigned>(__cvta_generic_to_shared(ptr));
}

__device__ __forceinline__ void ldsm4(unsigned& x0, unsigned& x1,
                                      unsigned& x2, unsigned& x3, unsigned addr)
{
    asm volatile("ldmatrix.sync.aligned.m8n8.x4.shared.b16 {%0,%1,%2,%3}, [%4];"
                 : "=r"(x0), "=r"(x1), "=r"(x2), "=r"(x3)
                 : "r"(addr));
}

__device__ __forceinline__ void ldsm4t(unsigned& x0, unsigned& x1,
                                       unsigned& x2, unsigned& x3, unsigned addr)
{
    asm volatile("ldmatrix.sync.aligned.m8n8.x4.trans.shared.b16 {%0,%1,%2,%3}, [%4];"
                 : "=r"(x0), "=r"(x1), "=r"(x2), "=r"(x3)
                 : "r"(addr));
}

__device__ __forceinline__ void mma_16816(float& c0, float& c1, float& c2, float& c3,
                                          unsigned a0, unsigned a1, unsigned a2, unsigned a3,
                                          unsigned b0, unsigned b1)
{
    asm volatile(
        "mma.sync.aligned.m16n8k16.row.col.f32.f16.f16.f32 "
        "{%0,%1,%2,%3}, {%4,%5,%6,%7}, {%8,%9}, {%0,%1,%2,%3};"
        : "+f"(c0), "+f"(c1), "+f"(c2), "+f"(c3)
        : "r"(a0), "r"(a1), "r"(a2), "r"(a3), "r"(b0), "r"(b1));
}

// ===========================================================================
// Tensor-core GEMM: hw[M,128] = h[M,256] @ W[256,128]
// fp32 -> fp16 in smem, fp32 accumulate, fp16 store to g_hw.
// 256 threads = 8 warps in 4(M) x 2(N); warp tile 32x64; block 128x128, BK=32.
// ===========================================================================
#define GBM 128
#define A_PAD 40    // halves per Ash row (80 B)
#define B_PAD 136   // halves per Bsh row (272 B)

__global__ __launch_bounds__(256) void gemm_kernel(
    const float* __restrict__ hmat, const float* __restrict__ wmat, int M)
{
    __shared__ __align__(16) __half Ash[128][A_PAD];
    __shared__ __align__(16) __half Bsh[32][B_PAD];

    const int tid    = threadIdx.x;
    const int lane   = tid & 31;
    const int wid    = tid >> 5;
    const int warp_m = wid & 3;
    const int warp_n = wid >> 2;
    const int block_m = blockIdx.x * GBM;

    float acc[2][8][4];
#pragma unroll
    for (int mt = 0; mt < 2; mt++) {
#pragma unroll
        for (int nt = 0; nt < 8; nt++) {
#pragma unroll
            for (int q = 0; q < 4; q++) {
                acc[mt][nt][q] = 0.0f;
            }
        }
    }

    const int ldrow = lane & 15;           // row within 16-row tile
    const int ldcol = (lane >> 4) * 8;     // 0 or 8 halves

    for (int k0 = 0; k0 < IN_FEATS; k0 += 32) {
        // ---- stage A tile: 128 rows x 32 halves (each thread: 8 floats) ----
#pragma unroll
        for (int rep = 0; rep < 2; rep++) {
            int seg  = tid + rep * 256;        // 0..511
            int arow = seg >> 2;               // 0..127
            int acol = (seg & 3) * 8;          // 0,8,16,24
            int grow = block_m + arow;
            float4 va = make_float4(0.0f, 0.0f, 0.0f, 0.0f);
            float4 vb = make_float4(0.0f, 0.0f, 0.0f, 0.0f);
            if (grow < M) {
                const float* ptr = hmat + (size_t)grow * IN_FEATS + k0 + acol;
                va = reinterpret_cast<const float4*>(ptr)[0];
                vb = reinterpret_cast<const float4*>(ptr)[1];
            }
            __half2 pk[4];
            pk[0] = __floats2half2_rn(va.x, va.y);
            pk[1] = __floats2half2_rn(va.z, va.w);
            pk[2] = __floats2half2_rn(vb.x, vb.y);
            pk[3] = __floats2half2_rn(vb.z, vb.w);
            *reinterpret_cast<uint4*>(&Ash[arow][acol]) =
                *reinterpret_cast<const uint4*>(pk);
        }
        // ---- stage B tile: 32 rows x 128 halves ----
#pragma unroll
        for (int rep = 0; rep < 2; rep++) {
            int seg  = tid + rep * 256;        // 0..511
            int brow = seg >> 4;               // 0..31
            int bcol = (seg & 15) * 8;         // 0..120
            const float* ptr = wmat + (size_t)(k0 + brow) * OUT_FEATS + bcol;
            float4 va = reinterpret_cast<const float4*>(ptr)[0];
            float4 vb = reinterpret_cast<const float4*>(ptr)[1];
            __half2 pk[4];
            pk[0] = __floats2half2_rn(va.x, va.y);
            pk[1] = __floats2half2_rn(va.z, va.w);
            pk[2] = __floats2half2_rn(vb.x, vb.y);
            pk[3] = __floats2half2_rn(vb.z, vb.w);
            *reinterpret_cast<uint4*>(&Bsh[brow][bcol]) =
                *reinterpret_cast<const uint4*>(pk);
        }
        __syncthreads();

        // ---- compute: two k16 steps ----
#pragma unroll
        for (int kk = 0; kk < 32; kk += 16) {
            unsigned afrag[2][4];
#pragma unroll
            for (int mt = 0; mt < 2; mt++) {
                unsigned addr = smem_addr_u32(
                    &Ash[warp_m * 32 + mt * 16 + ldrow][kk + ldcol]);
                ldsm4(afrag[mt][0], afrag[mt][1], afrag[mt][2], afrag[mt][3], addr);
            }
            unsigned bfrag[4][4];
#pragma unroll
            for (int pp = 0; pp < 4; pp++) {
                unsigned addr = smem_addr_u32(
                    &Bsh[kk + ldrow][warp_n * 64 + pp * 16 + ldcol]);
                ldsm4t(bfrag[pp][0], bfrag[pp][1], bfrag[pp][2], bfrag[pp][3], addr);
            }
#pragma unroll
            for (int mt = 0; mt < 2; mt++) {
#pragma unroll
                for (int nt = 0; nt < 8; nt++) {
                    unsigned bu0 = bfrag[nt >> 1][(nt & 1) * 2];
                    unsigned bu1 = bfrag[nt >> 1][(nt & 1) * 2 + 1];
                    mma_16816(acc[mt][nt][0], acc[mt][nt][1],
                              acc[mt][nt][2], acc[mt][nt][3],
                              afrag[mt][0], afrag[mt][1],
                              afrag[mt][2], afrag[mt][3], bu0, bu1);
                }
            }
        }
        __syncthreads();
    }

    // ---- epilogue: fp16 store of C fragments ----
    const int qrow = lane >> 2;    // 0..7
    const int qcol = lane & 3;     // 0..3
#pragma unroll
    for (int mt = 0; mt < 2; mt++) {
#pragma unroll
        for (int nt = 0; nt < 8; nt++) {
            int col  = warp_n * 64 + nt * 8 + qcol * 2;
            int row0 = block_m + warp_m * 32 + mt * 16 + qrow;
            int row1 = row0 + 8;
            if (row0 < M) {
                *reinterpret_cast<__half2*>(&g_hw[(size_t)row0 * OUT_FEATS + col]) =
                    __floats2half2_rn(acc[mt][nt][0], acc[mt][nt][1]);
            }
            if (row1 < M) {
                *reinterpret_cast<__half2*>(&g_hw[(size_t)row1 * OUT_FEATS + col]) =
                    __floats2half2_rn(acc[mt][nt][2], acc[mt][nt][3]);
            }
        }
    }
}

// ===========================================================================
// CSR build (all known-good kernels from rounds 3/4, verbatim)
// ===========================================================================
__global__ void zero_counts_kernel(int N)
{
    int i = blockIdx.x * blockDim.x + threadIdx.x;
    if (i < N) g_counts[i] = 0;
}

__global__ void hist_kernel(const int* __restrict__ dst, int E)
{
    int e = blockIdx.x * blockDim.x + threadIdx.x;
    if (e < E) atomicAdd(&g_counts[dst[e]], 1);
}

__global__ __launch_bounds__(256) void scan_sums_kernel(int N)
{
    __shared__ int sh[256];
    int i = blockIdx.x * 256 + threadIdx.x;
    sh[threadIdx.x] = (i < N) ? g_counts[i] : 0;
    __syncthreads();
#pragma unroll
    for (int s = 128; s > 0; s >>= 1) {
        if (threadIdx.x < s) sh[threadIdx.x] += sh[threadIdx.x + s];
        __syncthreads();
    }
    if (threadIdx.x == 0) g_bsum[blockIdx.x] = sh[0];
}

__global__ __launch_bounds__(256) void scan_top_kernel(int nb, int N, int E)
{
    __shared__ int sh[256];
    int t = threadIdx.x;
    int v = (t < nb) ? g_bsum[t] : 0;
    sh[t] = v;
    __syncthreads();
#pragma unroll
    for (int s = 1; s < 256; s <<= 1) {
        int add = (t >= s) ? sh[t - s] : 0;
        __syncthreads();
        sh[t] += add;
        __syncthreads();
    }
    if (t < nb) g_boff[t] = sh[t] - v;
    if (t == 0) g_row_ptr[N] = E;
}

__global__ __launch_bounds__(256) void scan_write_kernel(int N)
{
    __shared__ int sh[256];
    int t = threadIdx.x;
    int i = blockIdx.x * 256 + t;
    int v = (i < N) ? g_counts[i] : 0;
    sh[t] = v;
    __syncthreads();
#pragma unroll
    for (int s = 1; s < 256; s <<= 1) {
        int add = (t >= s) ? sh[t - s] : 0;
        __syncthreads();
        sh[t] += add;
        __syncthreads();
    }
    if (i < N) {
        int rp = g_boff[blockIdx.x] + sh[t] - v;
        g_row_ptr[i] = rp;
        g_cursor[i]  = rp;
    }
}

__global__ void permute_kernel(
    const int* __restrict__ src, const int* __restrict__ dst,
    const float* __restrict__ norm, const float* __restrict__ ew, int E)
{
    int e = blockIdx.x * blockDim.x + threadIdx.x;
    if (e >= E) return;
    int s = src[e];
    int d = dst[e];
    int pos = atomicAdd(&g_cursor[d], 1);
    g_perm_src[pos] = s;
    g_perm_c[pos]   = norm[s] * ew[e];
}

// ===========================================================================
// Gather-aggregate per destination node + fused finalize (round-4 version).
// One warp per node; lane handles 4 features (8 bytes of fp16 per edge).
// ===========================================================================
__global__ __launch_bounds__(256) void gather_kernel(
    const float* __restrict__ norm, const float* __restrict__ bias,
    float* __restrict__ out, int N)
{
    int d = blockIdx.x * 8 + (threadIdx.x >> 5);
    if (d >= N) return;
    int lane = threadIdx.x & 31;

    int j   = g_row_ptr[d];
    int end = g_row_ptr[d + 1];

    float ax = 0.f, ay = 0.f, az = 0.f, aw = 0.f;

    for (; j + 2 <= end; j += 2) {
        int   s0 = g_perm_src[j],   s1 = g_perm_src[j + 1];
        float c0 = g_perm_c[j],     c1 = g_perm_c[j + 1];
        uint2 r0 = *reinterpret_cast<const uint2*>(&g_hw[(size_t)s0 * OUT_FEATS + lane * 4]);
        uint2 r1 = *reinterpret_cast<const uint2*>(&g_hw[(size_t)s1 * OUT_FEATS + lane * 4]);
        float2 f00 = __half22float2(*reinterpret_cast<__half2*>(&r0.x));
        float2 f01 = __half22float2(*reinterpret_cast<__half2*>(&r0.y));
        float2 f10 = __half22float2(*reinterpret_cast<__half2*>(&r1.x));
        float2 f11 = __half22float2(*reinterpret_cast<__half2*>(&r1.y));
        ax = fmaf(c0, f00.x, ax); ay = fmaf(c0, f00.y, ay);
        az = fmaf(c0, f01.x, az); aw = fmaf(c0, f01.y, aw);
        ax = fmaf(c1, f10.x, ax); ay = fmaf(c1, f10.y, ay);
        az = fmaf(c1, f11.x, az); aw = fmaf(c1, f11.y, aw);
    }
    if (j < end) {
        int   s0 = g_perm_src[j];
        float c0 = g_perm_c[j];
        uint2 r0 = *reinterpret_cast<const uint2*>(&g_hw[(size_t)s0 * OUT_FEATS + lane * 4]);
        float2 f00 = __half22float2(*reinterpret_cast<__half2*>(&r0.x));
        float2 f01 = __half22float2(*reinterpret_cast<__half2*>(&r0.y));
        ax = fmaf(c0, f00.x, ax); ay = fmaf(c0, f00.y, ay);
        az = fmaf(c0, f01.x, az); aw = fmaf(c0, f01.y, aw);
    }

    float  nd = norm[d];
    float4 bb = reinterpret_cast<const float4*>(bias)[lane];
    float4 rr;
    rr.x = fmaxf(fmaf(ax, nd, bb.x), 0.f);
    rr.y = fmaxf(fmaf(ay, nd, bb.y), 0.f);
    rr.z = fmaxf(fmaf(az, nd, bb.z), 0.f);
    rr.w = fmaxf(fmaf(aw, nd, bb.w), 0.f);
    reinterpret_cast<float4*>(out)[(size_t)d * 32 + lane] = rr;
}

// ===========================================================================
// Launch. GEMM at launch index 3 (the slot ncu empirically profiles).
// ===========================================================================
extern "C" void kernel_launch(void* const* d_in, const int* in_sizes, int n_in,
                              void* d_out, int out_size)
{
    const float* h    = (const float*)d_in[0];
    const float* W    = (const float*)d_in[1];
    const float* bias = (const float*)d_in[2];
    const float* norm = (const float*)d_in[3];
    const float* ew   = (const float*)d_in[4];
    const int*   src  = (const int*)d_in[5];
    const int*   dst  = (const int*)d_in[6];
    float* out = (float*)d_out;

    const int N  = in_sizes[3];
    const int E  = in_sizes[4];
    const int nb = (N + 255) / 256;

    zero_counts_kernel<<<nb, 256>>>(N);                              // 0
    hist_kernel<<<(E + 255) / 256, 256>>>(dst, E);                   // 1
    scan_sums_kernel<<<nb, 256>>>(N);                                // 2
    gemm_kernel<<<(N + GBM - 1) / GBM, 256>>>(h, W, N);              // 3 (profiled)
    scan_top_kernel<<<1, 256>>>(nb, N, E);                           // 4
    scan_write_kernel<<<nb, 256>>>(N);                               // 5
    permute_kernel<<<(E + 255) / 256, 256>>>(src, dst, norm, ew, E); // 6
    gather_kernel<<<(N + 7) / 8, 256>>>(norm, bias, out, N);         // 7
}

// round 7
// speedup vs baseline: 1.9906x; 1.0177x over previous
#include <cuda_runtime.h>
#include <cuda_fp16.h>

#define N_NODES   50000
#define IN_FEATS  256
#define OUT_FEATS 128
#define MAX_E     800000

// ---- scratch (device globals; no allocs allowed) ----
__device__ __half g_hw[(size_t)N_NODES * OUT_FEATS];  // projected features (fp16)
__device__ int    g_counts[N_NODES];
__device__ int    g_row_ptr[N_NODES + 1];
__device__ int    g_cursor[N_NODES];
__device__ int    g_bsum[256];
__device__ int    g_boff[256];
__device__ int    g_perm_src[MAX_E];
__device__ float  g_perm_c[MAX_E];

// ===========================================================================
// PTX helpers
// ===========================================================================
__device__ __forceinline__ unsigned smem_addr_u32(const void* ptr)
{
    return static_cast<unsigned>(__cvta_generic_to_shared(ptr));
}

__device__ __forceinline__ void ldsm4(unsigned& x0, unsigned& x1,
                                      unsigned& x2, unsigned& x3, unsigned addr)
{
    asm volatile("ldmatrix.sync.aligned.m8n8.x4.shared.b16 {%0,%1,%2,%3}, [%4];"
                 : "=r"(x0), "=r"(x1), "=r"(x2), "=r"(x3)
                 : "r"(addr));
}

__device__ __forceinline__ void ldsm4t(unsigned& x0, unsigned& x1,
                                       unsigned& x2, unsigned& x3, unsigned addr)
{
    asm volatile("ldmatrix.sync.aligned.m8n8.x4.trans.shared.b16 {%0,%1,%2,%3}, [%4];"
                 : "=r"(x0), "=r"(x1), "=r"(x2), "=r"(x3)
                 : "r"(addr));
}

__device__ __forceinline__ void mma_16816(float& c0, float& c1, float& c2, float& c3,
                                          unsigned a0, unsigned a1, unsigned a2, unsigned a3,
                                          unsigned b0, unsigned b1)
{
    asm volatile(
        "mma.sync.aligned.m16n8k16.row.col.f32.f16.f16.f32 "
        "{%0,%1,%2,%3}, {%4,%5,%6,%7}, {%8,%9}, {%0,%1,%2,%3};"
        : "+f"(c0), "+f"(c1), "+f"(c2), "+f"(c3)
        : "r"(a0), "r"(a1), "r"(a2), "r"(a3), "r"(b0), "r"(b1));
}

// ===========================================================================
// Tensor-core GEMM, double-buffered: hw[M,128] = h[M,256] @ W[256,128]
// fp32 loads staged in registers while current tile computes; fp16 smem;
// fp32 accumulate; fp16 store to g_hw.
// 256 threads = 8 warps in 4(M) x 2(N); warp tile 32x64; block 128x128, BK=32.
// ===========================================================================
#define GBM 128
#define A_PAD 40    // halves per Ash row (80 B)
#define B_PAD 136   // halves per Bsh row (272 B)

__global__ __launch_bounds__(256) void gemm_kernel(
    const float* __restrict__ hmat, const float* __restrict__ wmat, int M)
{
    __shared__ __align__(16) __half Ash[2][128][A_PAD];
    __shared__ __align__(16) __half Bsh[2][32][B_PAD];

    const int tid    = threadIdx.x;
    const int lane   = tid & 31;
    const int wid    = tid >> 5;
    const int warp_m = wid & 3;
    const int warp_n = wid >> 2;
    const int block_m = blockIdx.x * GBM;

    // per-thread load coordinates (constant across k-loop)
    const int arow0 = tid >> 2;                 // rep 0: rows 0..63
    const int arow1 = (tid + 256) >> 2;         // rep 1: rows 64..127
    const int acol0 = (tid & 3) * 8;
    const int brow0 = tid >> 4;                 // rep 0: rows 0..15
    const int brow1 = (tid + 256) >> 4;         // rep 1: rows 16..31
    const int bcol0 = (tid & 15) * 8;

    float acc[2][8][4];
#pragma unroll
    for (int mt = 0; mt < 2; mt++)
#pragma unroll
        for (int nt = 0; nt < 8; nt++)
#pragma unroll
            for (int q = 0; q < 4; q++) acc[mt][nt][q] = 0.0f;

    const int ldrow = lane & 15;
    const int ldcol = (lane >> 4) * 8;

    float4 stA[2][2];   // [rep][float4 pair]
    float4 stB[2][2];

    // ---------------- prologue: load + stage tile k0 = 0 ----------------
    {
        const int grow0 = block_m + arow0;
        const int grow1 = block_m + arow1;
        stA[0][0] = stA[0][1] = make_float4(0.f, 0.f, 0.f, 0.f);
        stA[1][0] = stA[1][1] = make_float4(0.f, 0.f, 0.f, 0.f);
        if (grow0 < M) {
            const float* p = hmat + (size_t)grow0 * IN_FEATS + acol0;
            stA[0][0] = reinterpret_cast<const float4*>(p)[0];
            stA[0][1] = reinterpret_cast<const float4*>(p)[1];
        }
        if (grow1 < M) {
            const float* p = hmat + (size_t)grow1 * IN_FEATS + acol0;
            stA[1][0] = reinterpret_cast<const float4*>(p)[0];
            stA[1][1] = reinterpret_cast<const float4*>(p)[1];
        }
        {
            const float* p = wmat + (size_t)brow0 * OUT_FEATS + bcol0;
            stB[0][0] = reinterpret_cast<const float4*>(p)[0];
            stB[0][1] = reinterpret_cast<const float4*>(p)[1];
        }
        {
            const float* p = wmat + (size_t)brow1 * OUT_FEATS + bcol0;
            stB[1][0] = reinterpret_cast<const float4*>(p)[0];
            stB[1][1] = reinterpret_cast<const float4*>(p)[1];
        }
        // store into buffer 0
        __half2 pk[4];
        pk[0] = __floats2half2_rn(stA[0][0].x, stA[0][0].y);
        pk[1] = __floats2half2_rn(stA[0][0].z, stA[0][0].w);
        pk[2] = __floats2half2_rn(stA[0][1].x, stA[0][1].y);
        pk[3] = __floats2half2_rn(stA[0][1].z, stA[0][1].w);
        *reinterpret_cast<uint4*>(&Ash[0][arow0][acol0]) = *reinterpret_cast<const uint4*>(pk);
        pk[0] = __floats2half2_rn(stA[1][0].x, stA[1][0].y);
        pk[1] = __floats2half2_rn(stA[1][0].z, stA[1][0].w);
        pk[2] = __floats2half2_rn(stA[1][1].x, stA[1][1].y);
        pk[3] = __floats2half2_rn(stA[1][1].z, stA[1][1].w);
        *reinterpret_cast<uint4*>(&Ash[0][arow1][acol0]) = *reinterpret_cast<const uint4*>(pk);
        pk[0] = __floats2half2_rn(stB[0][0].x, stB[0][0].y);
        pk[1] = __floats2half2_rn(stB[0][0].z, stB[0][0].w);
        pk[2] = __floats2half2_rn(stB[0][1].x, stB[0][1].y);
        pk[3] = __floats2half2_rn(stB[0][1].z, stB[0][1].w);
        *reinterpret_cast<uint4*>(&Bsh[0][brow0][bcol0]) = *reinterpret_cast<const uint4*>(pk);
        pk[0] = __floats2half2_rn(stB[1][0].x, stB[1][0].y);
        pk[1] = __floats2half2_rn(stB[1][0].z, stB[1][0].w);
        pk[2] = __floats2half2_rn(stB[1][1].x, stB[1][1].y);
        pk[3] = __floats2half2_rn(stB[1][1].z, stB[1][1].w);
        *reinterpret_cast<uint4*>(&Bsh[0][brow1][bcol0]) = *reinterpret_cast<const uint4*>(pk);
    }
    __syncthreads();

    // ---------------- main loop ----------------
    int buf = 0;
    for (int k0 = 0; k0 < IN_FEATS; k0 += 32, buf ^= 1) {
        const bool has_next = (k0 + 32 < IN_FEATS);

        // issue next tile's global loads early (latency overlapped w/ MMA)
        if (has_next) {
            const int kn = k0 + 32;
            const int grow0 = block_m + arow0;
            const int grow1 = block_m + arow1;
            stA[0][0] = stA[0][1] = make_float4(0.f, 0.f, 0.f, 0.f);
            stA[1][0] = stA[1][1] = make_float4(0.f, 0.f, 0.f, 0.f);
            if (grow0 < M) {
                const float* p = hmat + (size_t)grow0 * IN_FEATS + kn + acol0;
                stA[0][0] = reinterpret_cast<const float4*>(p)[0];
                stA[0][1] = reinterpret_cast<const float4*>(p)[1];
            }
            if (grow1 < M) {
                const float* p = hmat + (size_t)grow1 * IN_FEATS + kn + acol0;
                stA[1][0] = reinterpret_cast<const float4*>(p)[0];
                stA[1][1] = reinterpret_cast<const float4*>(p)[1];
            }
            {
                const float* p = wmat + (size_t)(kn + brow0) * OUT_FEATS + bcol0;
                stB[0][0] = reinterpret_cast<const float4*>(p)[0];
                stB[0][1] = reinterpret_cast<const float4*>(p)[1];
            }
            {
                const float* p = wmat + (size_t)(kn + brow1) * OUT_FEATS + bcol0;
                stB[1][0] = reinterpret_cast<const float4*>(p)[0];
                stB[1][1] = reinterpret_cast<const float4*>(p)[1];
            }
        }

        // compute on current buffer
#pragma unroll
        for (int kk = 0; kk < 32; kk += 16) {
            unsigned afrag[2][4];
#pragma unroll
            for (int mt = 0; mt < 2; mt++) {
                unsigned addr = smem_addr_u32(
                    &Ash[buf][warp_m * 32 + mt * 16 + ldrow][kk + ldcol]);
                ldsm4(afrag[mt][0], afrag[mt][1], afrag[mt][2], afrag[mt][3], addr);
            }
            unsigned bfrag[4][4];
#pragma unroll
            for (int pp = 0; pp < 4; pp++) {
                unsigned addr = smem_addr_u32(
                    &Bsh[buf][kk + ldrow][warp_n * 64 + pp * 16 + ldcol]);
                ldsm4t(bfrag[pp][0], bfrag[pp][1], bfrag[pp][2], bfrag[pp][3], addr);
            }
#pragma unroll
            for (int mt = 0; mt < 2; mt++) {
#pragma unroll
                for (int nt = 0; nt < 8; nt++) {
                    unsigned bu0 = bfrag[nt >> 1][(nt & 1) * 2];
                    unsigned bu1 = bfrag[nt >> 1][(nt & 1) * 2 + 1];
                    mma_16816(acc[mt][nt][0], acc[mt][nt][1],
                              acc[mt][nt][2], acc[mt][nt][3],
                              afrag[mt][0], afrag[mt][1],
                              afrag[mt][2], afrag[mt][3], bu0, bu1);
                }
            }
        }

        // stage next tile into the other buffer
        if (has_next) {
            const int nb_ = buf ^ 1;
            __half2 pk[4];
            pk[0] = __floats2half2_rn(stA[0][0].x, stA[0][0].y);
            pk[1] = __floats2half2_rn(stA[0][0].z, stA[0][0].w);
            pk[2] = __floats2half2_rn(stA[0][1].x, stA[0][1].y);
            pk[3] = __floats2half2_rn(stA[0][1].z, stA[0][1].w);
            *reinterpret_cast<uint4*>(&Ash[nb_][arow0][acol0]) = *reinterpret_cast<const uint4*>(pk);
            pk[0] = __floats2half2_rn(stA[1][0].x, stA[1][0].y);
            pk[1] = __floats2half2_rn(stA[1][0].z, stA[1][0].w);
            pk[2] = __floats2half2_rn(stA[1][1].x, stA[1][1].y);
            pk[3] = __floats2half2_rn(stA[1][1].z, stA[1][1].w);
            *reinterpret_cast<uint4*>(&Ash[nb_][arow1][acol0]) = *reinterpret_cast<const uint4*>(pk);
            pk[0] = __floats2half2_rn(stB[0][0].x, stB[0][0].y);
            pk[1] = __floats2half2_rn(stB[0][0].z, stB[0][0].w);
            pk[2] = __floats2half2_rn(stB[0][1].x, stB[0][1].y);
            pk[3] = __floats2half2_rn(stB[0][1].z, stB[0][1].w);
            *reinterpret_cast<uint4*>(&Bsh[nb_][brow0][bcol0]) = *reinterpret_cast<const uint4*>(pk);
            pk[0] = __floats2half2_rn(stB[1][0].x, stB[1][0].y);
            pk[1] = __floats2half2_rn(stB[1][0].z, stB[1][0].w);
            pk[2] = __floats2half2_rn(stB[1][1].x, stB[1][1].y);
            pk[3] = __floats2half2_rn(stB[1][1].z, stB[1][1].w);
            *reinterpret_cast<uint4*>(&Bsh[nb_][brow1][bcol0]) = *reinterpret_cast<const uint4*>(pk);
        }
        __syncthreads();
    }

    // ---- epilogue: fp16 store of C fragments ----
    const int qrow = lane >> 2;
    const int qcol = lane & 3;
#pragma unroll
    for (int mt = 0; mt < 2; mt++) {
#pragma unroll
        for (int nt = 0; nt < 8; nt++) {
            int col  = warp_n * 64 + nt * 8 + qcol * 2;
            int row0 = block_m + warp_m * 32 + mt * 16 + qrow;
            int row1 = row0 + 8;
            if (row0 < M) {
                *reinterpret_cast<__half2*>(&g_hw[(size_t)row0 * OUT_FEATS + col]) =
                    __floats2half2_rn(acc[mt][nt][0], acc[mt][nt][1]);
            }
            if (row1 < M) {
                *reinterpret_cast<__half2*>(&g_hw[(size_t)row1 * OUT_FEATS + col]) =
                    __floats2half2_rn(acc[mt][nt][2], acc[mt][nt][3]);
            }
        }
    }
}

// ===========================================================================
// CSR build
// ===========================================================================
__global__ void zero_counts_kernel(int N)
{
    int i = blockIdx.x * blockDim.x + threadIdx.x;
    if (i < N) g_counts[i] = 0;
}

// ILP-4 histogram: vectorized dst loads, 4 atomics in flight per thread.
__global__ void hist_kernel(const int* __restrict__ dst, int E)
{
    int base = (blockIdx.x * blockDim.x + threadIdx.x) * 4;
    if (base + 4 <= E) {
        int4 d4 = *reinterpret_cast<const int4*>(dst + base);
        atomicAdd(&g_counts[d4.x], 1);
        atomicAdd(&g_counts[d4.y], 1);
        atomicAdd(&g_counts[d4.z], 1);
        atomicAdd(&g_counts[d4.w], 1);
    } else {
        for (int k = base; k < E; k++) atomicAdd(&g_counts[dst[k]], 1);
    }
}

__global__ __launch_bounds__(256) void scan_sums_kernel(int N)
{
    __shared__ int sh[256];
    int i = blockIdx.x * 256 + threadIdx.x;
    sh[threadIdx.x] = (i < N) ? g_counts[i] : 0;
    __syncthreads();
#pragma unroll
    for (int s = 128; s > 0; s >>= 1) {
        if (threadIdx.x < s) sh[threadIdx.x] += sh[threadIdx.x + s];
        __syncthreads();
    }
    if (threadIdx.x == 0) g_bsum[blockIdx.x] = sh[0];
}

__global__ __launch_bounds__(256) void scan_top_kernel(int nb, int N, int E)
{
    __shared__ int sh[256];
    int t = threadIdx.x;
    int v = (t < nb) ? g_bsum[t] : 0;
    sh[t] = v;
    __syncthreads();
#pragma unroll
    for (int s = 1; s < 256; s <<= 1) {
        int add = (t >= s) ? sh[t - s] : 0;
        __syncthreads();
        sh[t] += add;
        __syncthreads();
    }
    if (t < nb) g_boff[t] = sh[t] - v;
    if (t == 0) g_row_ptr[N] = E;
}

__global__ __launch_bounds__(256) void scan_write_kernel(int N)
{
    __shared__ int sh[256];
    int t = threadIdx.x;
    int i = blockIdx.x * 256 + t;
    int v = (i < N) ? g_counts[i] : 0;
    sh[t] = v;
    __syncthreads();
#pragma unroll
    for (int s = 1; s < 256; s <<= 1) {
        int add = (t >= s) ? sh[t - s] : 0;
        __syncthreads();
        sh[t] += add;
        __syncthreads();
    }
    if (i < N) {
        int rp = g_boff[blockIdx.x] + sh[t] - v;
        g_row_ptr[i] = rp;
        g_cursor[i]  = rp;
    }
}

// ILP-4 permutation: vectorized edge loads, 4 norm gathers in flight,
// then atomic cursor bump + scatter.
__global__ void permute_kernel(
    const int* __restrict__ src, const int* __restrict__ dst,
    const float* __restrict__ norm, const float* __restrict__ ew, int E)
{
    int base = (blockIdx.x * blockDim.x + threadIdx.x) * 4;
    if (base + 4 <= E) {
        int4   s4 = *reinterpret_cast<const int4*>(src + base);
        int4   d4 = *reinterpret_cast<const int4*>(dst + base);
        float4 w4 = *reinterpret_cast<const float4*>(ew + base);
        float c0 = norm[s4.x] * w4.x;
        float c1 = norm[s4.y] * w4.y;
        float c2 = norm[s4.z] * w4.z;
        float c3 = norm[s4.w] * w4.w;
        int p0 = atomicAdd(&g_cursor[d4.x], 1);
        int p1 = atomicAdd(&g_cursor[d4.y], 1);
        int p2 = atomicAdd(&g_cursor[d4.z], 1);
        int p3 = atomicAdd(&g_cursor[d4.w], 1);
        g_perm_src[p0] = s4.x;  g_perm_c[p0] = c0;
        g_perm_src[p1] = s4.y;  g_perm_c[p1] = c1;
        g_perm_src[p2] = s4.z;  g_perm_c[p2] = c2;
        g_perm_src[p3] = s4.w;  g_perm_c[p3] = c3;
    } else {
        for (int k = base; k < E; k++) {
            int s = src[k];
            int d = dst[k];
            int pos = atomicAdd(&g_cursor[d], 1);
            g_perm_src[pos] = s;
            g_perm_c[pos]   = norm[s] * ew[k];
        }
    }
}

// ===========================================================================
// Gather-aggregate per destination node + fused finalize (round-6 verbatim).
// ===========================================================================
__global__ __launch_bounds__(256) void gather_kernel(
    const float* __restrict__ norm, const float* __restrict__ bias,
    float* __restrict__ out, int N)
{
    int d = blockIdx.x * 8 + (threadIdx.x >> 5);
    if (d >= N) return;
    int lane = threadIdx.x & 31;

    int j   = g_row_ptr[d];
    int end = g_row_ptr[d + 1];

    float ax = 0.f, ay = 0.f, az = 0.f, aw = 0.f;

    for (; j + 2 <= end; j += 2) {
        int   s0 = g_perm_src[j],   s1 = g_perm_src[j + 1];
        float c0 = g_perm_c[j],     c1 = g_perm_c[j + 1];
        uint2 r0 = *reinterpret_cast<const uint2*>(&g_hw[(size_t)s0 * OUT_FEATS + lane * 4]);
        uint2 r1 = *reinterpret_cast<const uint2*>(&g_hw[(size_t)s1 * OUT_FEATS + lane * 4]);
        float2 f00 = __half22float2(*reinterpret_cast<__half2*>(&r0.x));
        float2 f01 = __half22float2(*reinterpret_cast<__half2*>(&r0.y));
        float2 f10 = __half22float2(*reinterpret_cast<__half2*>(&r1.x));
        float2 f11 = __half22float2(*reinterpret_cast<__half2*>(&r1.y));
        ax = fmaf(c0, f00.x, ax); ay = fmaf(c0, f00.y, ay);
        az = fmaf(c0, f01.x, az); aw = fmaf(c0, f01.y, aw);
        ax = fmaf(c1, f10.x, ax); ay = fmaf(c1, f10.y, ay);
        az = fmaf(c1, f11.x, az); aw = fmaf(c1, f11.y, aw);
    }
    if (j < end) {
        int   s0 = g_perm_src[j];
        float c0 = g_perm_c[j];
        uint2 r0 = *reinterpret_cast<const uint2*>(&g_hw[(size_t)s0 * OUT_FEATS + lane * 4]);
        float2 f00 = __half22float2(*reinterpret_cast<__half2*>(&r0.x));
        float2 f01 = __half22float2(*reinterpret_cast<__half2*>(&r0.y));
        ax = fmaf(c0, f00.x, ax); ay = fmaf(c0, f00.y, ay);
        az = fmaf(c0, f01.x, az); aw = fmaf(c0, f01.y, aw);
    }

    float  nd = norm[d];
    float4 bb = reinterpret_cast<const float4*>(bias)[lane];
    float4 rr;
    rr.x = fmaxf(fmaf(ax, nd, bb.x), 0.f);
    rr.y = fmaxf(fmaf(ay, nd, bb.y), 0.f);
    rr.z = fmaxf(fmaf(az, nd, bb.z), 0.f);
    rr.w = fmaxf(fmaf(aw, nd, bb.w), 0.f);
    reinterpret_cast<float4*>(out)[(size_t)d * 32 + lane] = rr;
}

// ===========================================================================
// Launch. GEMM at launch index 3 (the slot ncu empirically profiles).
// ===========================================================================
extern "C" void kernel_launch(void* const* d_in, const int* in_sizes, int n_in,
                              void* d_out, int out_size)
{
    const float* h    = (const float*)d_in[0];
    const float* W    = (const float*)d_in[1];
    const float* bias = (const float*)d_in[2];
    const float* norm = (const float*)d_in[3];
    const float* ew   = (const float*)d_in[4];
    const int*   src  = (const int*)d_in[5];
    const int*   dst  = (const int*)d_in[6];
    float* out = (float*)d_out;

    const int N  = in_sizes[3];
    const int E  = in_sizes[4];
    const int nb = (N + 255) / 256;

    zero_counts_kernel<<<nb, 256>>>(N);                                        // 0
    hist_kernel<<<(E + 4 * 256 - 1) / (4 * 256), 256>>>(dst, E);               // 1
    scan_sums_kernel<<<nb, 256>>>(N);                                          // 2
    gemm_kernel<<<(N + GBM - 1) / GBM, 256>>>(h, W, N);                        // 3 (profiled)
    scan_top_kernel<<<1, 256>>>(nb, N, E);                                     // 4
    scan_write_kernel<<<nb, 256>>>(N);                                         // 5
    permute_kernel<<<(E + 4 * 256 - 1) / (4 * 256), 256>>>(src, dst, norm, ew, E); // 6
    gather_kernel<<<(N + 7) / 8, 256>>>(norm, bias, out, N);                   // 7
}